// round 15
// baseline (speedup 1.0000x reference)
#include <cuda_runtime.h>
#include <cuda_bf16.h>
#include <cstdint>
#include <cstddef>

// ============================================================================
// out[8192,8192] = Q(x)[8192,2048] @ Q(w)[8192,2048]^T,  Q = e4m3 quant-dequant
// Legacy mma.sync m16n8k32 e4m3 (base-ISA; tcgen05 rejected by sm_103 target).
// R15 = byte-exact resubmit of the R14 champion (680.3us):
//   - MLP=4 fused quant (4x float4 -> uint4 per thread)
//   - GEMM: 128x128x128 tile, 8 warps (4Mx2N, warp tile 32x64), 2-stage
//     cp.async double buffer, 2 CTAs/SM, XOR-folded SW128 addressing.
// Search converged: 5 perturbation families regressed (R5/R7/R8/R9/R10);
// geometry alternatives rejected analytically. Tensor ~69.5% is the
// practical legacy-QMMA ceiling at the 128-register occupancy cliff.
// ============================================================================
static constexpr int M_TOTAL = 8192;
static constexpr int N_TOTAL = 8192;
static constexpr int K_TOTAL = 2048;

static constexpr int BM = 128, BN = 128, BK = 128;   // BK in fp8 bytes
static constexpr int K_TILES = K_TOTAL / BK;          // 16
static constexpr int A_STAGE = BM * BK;               // 16384
static constexpr int B_STAGE = BN * BK;               // 16384
static constexpr int STAGE_BYTES = A_STAGE + B_STAGE; // 32768
static constexpr int SMEM_TOTAL = 2 * STAGE_BYTES;    // 65536

// FP8 scratch (allocation-free: __device__ globals)
__device__ __align__(16) uint8_t g_Aq[(size_t)M_TOTAL * K_TOTAL];
__device__ __align__(16) uint8_t g_Wq[(size_t)N_TOTAL * K_TOTAL];

// ---------------------------------------------------------------------------
__device__ __forceinline__ uint32_t smem_u32(const void* p) {
    uint32_t a;
    asm("{ .reg .u64 t; cvta.to.shared.u64 t, %1; cvt.u32.u64 %0, t; }"
        : "=r"(a) : "l"(p));
    return a;
}

#define CP_ASYNC16(smem, gmem) \
    asm volatile("cp.async.cg.shared.global [%0], [%1], 16;" \
        :: "r"(smem), "l"(gmem) : "memory")
#define CP_COMMIT() asm volatile("cp.async.commit_group;" ::: "memory")
#define CP_WAIT(n)  asm volatile("cp.async.wait_group %0;" :: "n"(n) : "memory")

#define SWZ(off) ((off) ^ (((off) >> 3) & 0x70))

__device__ __forceinline__ void ldmatrix_x4(uint32_t* r, uint32_t addr) {
    asm volatile("ldmatrix.sync.aligned.m8n8.x4.shared.b16 {%0,%1,%2,%3}, [%4];"
        : "=r"(r[0]), "=r"(r[1]), "=r"(r[2]), "=r"(r[3]) : "r"(addr));
}

__device__ __forceinline__ void mma_e4m3(float* c, const uint32_t* a,
                                         const uint32_t* b) {
    asm volatile(
        "mma.sync.aligned.m16n8k32.row.col.f32.e4m3.e4m3.f32 "
        "{%0,%1,%2,%3}, {%4,%5,%6,%7}, {%8,%9}, {%0,%1,%2,%3};"
        : "+f"(c[0]), "+f"(c[1]), "+f"(c[2]), "+f"(c[3])
        : "r"(a[0]), "r"(a[1]), "r"(a[2]), "r"(a[3]),
          "r"(b[0]), "r"(b[1]));
}

// ============================================================================
// Fused quantization, MLP=4: each thread converts 4 consecutive float4s
// (64B in) into one uint4 (16B out).
// ============================================================================
static constexpr int A_N4 = (M_TOTAL * K_TOTAL) / 4;  // float4 count in A
static constexpr int W_N4 = (N_TOTAL * K_TOTAL) / 4;  // float4 count in W
static constexpr int A_T4 = A_N4 / 4;                 // threads for A
static constexpr int W_T4 = W_N4 / 4;                 // threads for W

__device__ __forceinline__ uint32_t quant4(float4 v, float s) {
    uint16_t lo, hi;
    // cvt d, a, b -> d = {hi=a, lo=b}; byte0 = v.x
    asm("cvt.rn.satfinite.e4m3x2.f32 %0, %1, %2;"
        : "=h"(lo) : "f"(v.y * s), "f"(v.x * s));
    asm("cvt.rn.satfinite.e4m3x2.f32 %0, %1, %2;"
        : "=h"(hi) : "f"(v.w * s), "f"(v.z * s));
    return (uint32_t)lo | ((uint32_t)hi << 16);
}

__global__ void __launch_bounds__(256) quant_both_kernel(
    const float* __restrict__ x, const float* __restrict__ w,
    const float* __restrict__ sx, const float* __restrict__ sw,
    uint8_t* __restrict__ aq, uint8_t* __restrict__ wq)
{
    int i = blockIdx.x * blockDim.x + threadIdx.x;
    const float4* src;
    uint32_t* dst;
    float s;
    int j;   // float4 index of this thread's first chunk
    if (i < A_T4) {
        src = (const float4*)x; dst = (uint32_t*)aq; s = __ldg(sx); j = i * 4;
    } else {
        src = (const float4*)w; dst = (uint32_t*)wq; s = __ldg(sw);
        j = (i - A_T4) * 4;
    }
    // 4 independent loads (MLP=4)
    float4 v0 = src[j + 0];
    float4 v1 = src[j + 1];
    float4 v2 = src[j + 2];
    float4 v3 = src[j + 3];
    uint4 r;
    r.x = quant4(v0, s);
    r.y = quant4(v1, s);
    r.z = quant4(v2, s);
    r.w = quant4(v3, s);
    *reinterpret_cast<uint4*>(dst + j) = r;
}

// ============================================================================
// FP8 TN GEMM: CTA 128x128, 8 warps (4M x 2N), warp tile 32x64,
// 2-stage cp.async double buffer, all SMEM addresses precomputed.
// ============================================================================
__global__ void __launch_bounds__(256, 2) fp8_gemm_kernel(
    const uint8_t* __restrict__ Aq, const uint8_t* __restrict__ Wq,
    float* __restrict__ out,
    const float* __restrict__ sx, const float* __restrict__ sw)
{
    extern __shared__ char smem[];
    const uint32_t sbase = smem_u32(smem);
    const int tid  = threadIdx.x;
    const int lane = tid & 31;
    const int wid  = tid >> 5;
    const int warp_m = wid >> 1;   // 0..3
    const int warp_n = wid & 1;    // 0..1
    const int m0 = blockIdx.y * BM;
    const int n0 = blockIdx.x * BN;

    // ---- Precomputed cp.async mapping (constant across tiles) ----
    // chunk c = tid + i*256 -> row = c>>3, 16B-col = c&7
    uint32_t st_swo[4];     // swizzled SMEM offsets (same for A and B halves)
    uint32_t ld_aoff[4];    // gmem byte offsets into row-major [*,K] matrices
    {
#pragma unroll
        for (int i = 0; i < 4; i++) {
            int c   = tid + i * 256;
            int row = c >> 3;
            int c16 = (c & 7) << 4;
            st_swo[i]  = SWZ((uint32_t)(row * BK + c16));
            ld_aoff[i] = (uint32_t)(row * K_TOTAL + c16);
        }
    }
    const uint8_t* agbase = Aq + (size_t)m0 * K_TOTAL;
    const uint8_t* bgbase = Wq + (size_t)n0 * K_TOTAL;

    auto load_stage = [&](int slot, int kt) {
        const uint32_t abase = sbase + slot * STAGE_BYTES;
        const uint32_t koff  = (uint32_t)kt * BK;
#pragma unroll
        for (int i = 0; i < 4; i++) {
            CP_ASYNC16(abase + st_swo[i],           agbase + ld_aoff[i] + koff);
            CP_ASYNC16(abase + A_STAGE + st_swo[i], bgbase + ld_aoff[i] + koff);
        }
    };

    // Prologue
    load_stage(0, 0);
    CP_COMMIT();

    float acc[2][8][4];
#pragma unroll
    for (int mt = 0; mt < 2; mt++)
#pragma unroll
        for (int nt = 0; nt < 8; nt++)
#pragma unroll
            for (int q = 0; q < 4; q++) acc[mt][nt][q] = 0.0f;

    // ---- Precomputed swizzled fragment offsets (per warp, constant) ----
    // Pre-swizzle offsets have bits[6:5] = 0 (row*128 | hi<=16), so
    // SWZ(off + s*32) = SWZ(off) ^ (s*32).
    const int a_row = warp_m * 32 + (lane & 7) + ((lane >> 3) & 1) * 8;
    const int a_hi  = (lane >> 4) * 16;
    const int b_row = warp_n * 64 + (lane & 7) + (lane >> 4) * 8;
    const int b_hi  = ((lane >> 3) & 1) * 16;

    uint32_t a_sw[2], b_sw[4];
#pragma unroll
    for (int mt = 0; mt < 2; mt++)
        a_sw[mt] = SWZ((uint32_t)((a_row + mt * 16) * BK + a_hi));
#pragma unroll
    for (int p = 0; p < 4; p++)
        b_sw[p] = (uint32_t)A_STAGE + SWZ((uint32_t)((b_row + p * 16) * BK + b_hi));

    for (int kt = 0; kt < K_TILES; kt++) {
        CP_WAIT(0);
        __syncthreads();

        if (kt + 1 < K_TILES) {
            load_stage((kt + 1) & 1, kt + 1);
            CP_COMMIT();
        }

        const uint32_t abase = sbase + (kt & 1) * STAGE_BYTES;

#pragma unroll
        for (int s = 0; s < BK / 32; s++) {       // 4 k-steps of 32 fp8
            const uint32_t sx32 = (uint32_t)(s << 5);
            uint32_t af[2][4];
#pragma unroll
            for (int mt = 0; mt < 2; mt++)
                ldmatrix_x4(af[mt], abase + (a_sw[mt] ^ sx32));
            uint32_t bf[4][4];
#pragma unroll
            for (int p = 0; p < 4; p++)
                ldmatrix_x4(bf[p], abase + (b_sw[p] ^ sx32));
#pragma unroll
            for (int mt = 0; mt < 2; mt++)
#pragma unroll
                for (int p = 0; p < 4; p++) {
                    mma_e4m3(acc[mt][2 * p + 0], af[mt], &bf[p][0]);
                    mma_e4m3(acc[mt][2 * p + 1], af[mt], &bf[p][2]);
                }
        }
    }

    // Epilogue
    const float inv = 1.0f / (__ldg(sx) * __ldg(sw));
    const int r0 = m0 + warp_m * 32 + (lane >> 2);
    const int c0 = n0 + warp_n * 64 + (lane & 3) * 2;
#pragma unroll
    for (int mt = 0; mt < 2; mt++) {
#pragma unroll
        for (int nt = 0; nt < 8; nt++) {
            int row = r0 + mt * 16;
            int col = c0 + nt * 8;
            float2 v0 = { acc[mt][nt][0] * inv, acc[mt][nt][1] * inv };
            float2 v1 = { acc[mt][nt][2] * inv, acc[mt][nt][3] * inv };
            *reinterpret_cast<float2*>(out + (size_t)row * N_TOTAL + col) = v0;
            *reinterpret_cast<float2*>(out + (size_t)(row + 8) * N_TOTAL + col) = v1;
        }
    }
}

// ============================================================================
// kernel_launch
// ============================================================================
extern "C" void kernel_launch(void* const* d_in, const int* in_sizes, int n_in,
                              void* d_out, int out_size)
{
    const float* input  = (const float*)d_in[0];
    const float* weight = (const float*)d_in[1];
    const float* sx     = (const float*)d_in[2];  // input_scale_e4m3
    const float* sw     = (const float*)d_in[3];  // weight_scale_e4m3
    float* out = (float*)d_out;

    void* aq = nullptr;
    void* wq = nullptr;
    cudaGetSymbolAddress(&aq, g_Aq);
    cudaGetSymbolAddress(&wq, g_Wq);

    {
        int nthreads = A_T4 + W_T4;   // 2,097,152
        quant_both_kernel<<<nthreads / 256, 256>>>(input, weight, sx, sw,
                                                   (uint8_t*)aq, (uint8_t*)wq);
    }

    cudaFuncSetAttribute(fp8_gemm_kernel,
                         cudaFuncAttributeMaxDynamicSharedMemorySize, SMEM_TOTAL);
    dim3 grid(N_TOTAL / BN, M_TOTAL / BM);
    fp8_gemm_kernel<<<grid, 256, SMEM_TOTAL>>>(
        (const uint8_t*)aq, (const uint8_t*)wq, out, sx, sw);
}

// round 16
// speedup vs baseline: 1.0024x; 1.0024x over previous
#include <cuda_runtime.h>
#include <cuda_bf16.h>
#include <cstdint>
#include <cstddef>

// ============================================================================
// out[8192,8192] = Q(x)[8192,2048] @ Q(w)[8192,2048]^T,  Q = e4m3 quant-dequant
// Legacy mma.sync m16n8k32 e4m3 (base-ISA; tcgen05 rejected by sm_103 target).
// R16 = R14/R15 champion (680.3us) + ONE delta: mma asm is no longer
// `volatile`. The MMA is register-pure; dropping volatile removes the
// source-order fence between the 16 MMAs and the LDSM/address stream,
// letting nvcc/ptxas interleave freely. Zero added instructions/registers
// (the failure mode of every previous regression).
// ============================================================================
static constexpr int M_TOTAL = 8192;
static constexpr int N_TOTAL = 8192;
static constexpr int K_TOTAL = 2048;

static constexpr int BM = 128, BN = 128, BK = 128;   // BK in fp8 bytes
static constexpr int K_TILES = K_TOTAL / BK;          // 16
static constexpr int A_STAGE = BM * BK;               // 16384
static constexpr int B_STAGE = BN * BK;               // 16384
static constexpr int STAGE_BYTES = A_STAGE + B_STAGE; // 32768
static constexpr int SMEM_TOTAL = 2 * STAGE_BYTES;    // 65536

// FP8 scratch (allocation-free: __device__ globals)
__device__ __align__(16) uint8_t g_Aq[(size_t)M_TOTAL * K_TOTAL];
__device__ __align__(16) uint8_t g_Wq[(size_t)N_TOTAL * K_TOTAL];

// ---------------------------------------------------------------------------
__device__ __forceinline__ uint32_t smem_u32(const void* p) {
    uint32_t a;
    asm("{ .reg .u64 t; cvta.to.shared.u64 t, %1; cvt.u32.u64 %0, t; }"
        : "=r"(a) : "l"(p));
    return a;
}

#define CP_ASYNC16(smem, gmem) \
    asm volatile("cp.async.cg.shared.global [%0], [%1], 16;" \
        :: "r"(smem), "l"(gmem) : "memory")
#define CP_COMMIT() asm volatile("cp.async.commit_group;" ::: "memory")
#define CP_WAIT(n)  asm volatile("cp.async.wait_group %0;" :: "n"(n) : "memory")

#define SWZ(off) ((off) ^ (((off) >> 3) & 0x70))

__device__ __forceinline__ void ldmatrix_x4(uint32_t* r, uint32_t addr) {
    asm volatile("ldmatrix.sync.aligned.m8n8.x4.shared.b16 {%0,%1,%2,%3}, [%4];"
        : "=r"(r[0]), "=r"(r[1]), "=r"(r[2]), "=r"(r[3]) : "r"(addr));
}

// NOTE: intentionally NOT volatile — register-pure op; results all feed the
// epilogue so nothing is dead; data deps still order it after its ldmatrix
// producers. Gives the scheduler freedom to interleave.
__device__ __forceinline__ void mma_e4m3(float* c, const uint32_t* a,
                                         const uint32_t* b) {
    asm("mma.sync.aligned.m16n8k32.row.col.f32.e4m3.e4m3.f32 "
        "{%0,%1,%2,%3}, {%4,%5,%6,%7}, {%8,%9}, {%0,%1,%2,%3};"
        : "+f"(c[0]), "+f"(c[1]), "+f"(c[2]), "+f"(c[3])
        : "r"(a[0]), "r"(a[1]), "r"(a[2]), "r"(a[3]),
          "r"(b[0]), "r"(b[1]));
}

// ============================================================================
// Fused quantization, MLP=4: each thread converts 4 consecutive float4s
// (64B in) into one uint4 (16B out).
// ============================================================================
static constexpr int A_N4 = (M_TOTAL * K_TOTAL) / 4;  // float4 count in A
static constexpr int W_N4 = (N_TOTAL * K_TOTAL) / 4;  // float4 count in W
static constexpr int A_T4 = A_N4 / 4;                 // threads for A
static constexpr int W_T4 = W_N4 / 4;                 // threads for W

__device__ __forceinline__ uint32_t quant4(float4 v, float s) {
    uint16_t lo, hi;
    // cvt d, a, b -> d = {hi=a, lo=b}; byte0 = v.x
    asm("cvt.rn.satfinite.e4m3x2.f32 %0, %1, %2;"
        : "=h"(lo) : "f"(v.y * s), "f"(v.x * s));
    asm("cvt.rn.satfinite.e4m3x2.f32 %0, %1, %2;"
        : "=h"(hi) : "f"(v.w * s), "f"(v.z * s));
    return (uint32_t)lo | ((uint32_t)hi << 16);
}

__global__ void __launch_bounds__(256) quant_both_kernel(
    const float* __restrict__ x, const float* __restrict__ w,
    const float* __restrict__ sx, const float* __restrict__ sw,
    uint8_t* __restrict__ aq, uint8_t* __restrict__ wq)
{
    int i = blockIdx.x * blockDim.x + threadIdx.x;
    const float4* src;
    uint32_t* dst;
    float s;
    int j;   // float4 index of this thread's first chunk
    if (i < A_T4) {
        src = (const float4*)x; dst = (uint32_t*)aq; s = __ldg(sx); j = i * 4;
    } else {
        src = (const float4*)w; dst = (uint32_t*)wq; s = __ldg(sw);
        j = (i - A_T4) * 4;
    }
    // 4 independent loads (MLP=4)
    float4 v0 = src[j + 0];
    float4 v1 = src[j + 1];
    float4 v2 = src[j + 2];
    float4 v3 = src[j + 3];
    uint4 r;
    r.x = quant4(v0, s);
    r.y = quant4(v1, s);
    r.z = quant4(v2, s);
    r.w = quant4(v3, s);
    *reinterpret_cast<uint4*>(dst + j) = r;
}

// ============================================================================
// FP8 TN GEMM: CTA 128x128, 8 warps (4M x 2N), warp tile 32x64,
// 2-stage cp.async double buffer, all SMEM addresses precomputed.
// ============================================================================
__global__ void __launch_bounds__(256, 2) fp8_gemm_kernel(
    const uint8_t* __restrict__ Aq, const uint8_t* __restrict__ Wq,
    float* __restrict__ out,
    const float* __restrict__ sx, const float* __restrict__ sw)
{
    extern __shared__ char smem[];
    const uint32_t sbase = smem_u32(smem);
    const int tid  = threadIdx.x;
    const int lane = tid & 31;
    const int wid  = tid >> 5;
    const int warp_m = wid >> 1;   // 0..3
    const int warp_n = wid & 1;    // 0..1
    const int m0 = blockIdx.y * BM;
    const int n0 = blockIdx.x * BN;

    // ---- Precomputed cp.async mapping (constant across tiles) ----
    // chunk c = tid + i*256 -> row = c>>3, 16B-col = c&7
    uint32_t st_swo[4];     // swizzled SMEM offsets (same for A and B halves)
    uint32_t ld_aoff[4];    // gmem byte offsets into row-major [*,K] matrices
    {
#pragma unroll
        for (int i = 0; i < 4; i++) {
            int c   = tid + i * 256;
            int row = c >> 3;
            int c16 = (c & 7) << 4;
            st_swo[i]  = SWZ((uint32_t)(row * BK + c16));
            ld_aoff[i] = (uint32_t)(row * K_TOTAL + c16);
        }
    }
    const uint8_t* agbase = Aq + (size_t)m0 * K_TOTAL;
    const uint8_t* bgbase = Wq + (size_t)n0 * K_TOTAL;

    auto load_stage = [&](int slot, int kt) {
        const uint32_t abase = sbase + slot * STAGE_BYTES;
        const uint32_t koff  = (uint32_t)kt * BK;
#pragma unroll
        for (int i = 0; i < 4; i++) {
            CP_ASYNC16(abase + st_swo[i],           agbase + ld_aoff[i] + koff);
            CP_ASYNC16(abase + A_STAGE + st_swo[i], bgbase + ld_aoff[i] + koff);
        }
    };

    // Prologue
    load_stage(0, 0);
    CP_COMMIT();

    float acc[2][8][4];
#pragma unroll
    for (int mt = 0; mt < 2; mt++)
#pragma unroll
        for (int nt = 0; nt < 8; nt++)
#pragma unroll
            for (int q = 0; q < 4; q++) acc[mt][nt][q] = 0.0f;

    // ---- Precomputed swizzled fragment offsets (per warp, constant) ----
    // Pre-swizzle offsets have bits[6:5] = 0 (row*128 | hi<=16), so
    // SWZ(off + s*32) = SWZ(off) ^ (s*32).
    const int a_row = warp_m * 32 + (lane & 7) + ((lane >> 3) & 1) * 8;
    const int a_hi  = (lane >> 4) * 16;
    const int b_row = warp_n * 64 + (lane & 7) + (lane >> 4) * 8;
    const int b_hi  = ((lane >> 3) & 1) * 16;

    uint32_t a_sw[2], b_sw[4];
#pragma unroll
    for (int mt = 0; mt < 2; mt++)
        a_sw[mt] = SWZ((uint32_t)((a_row + mt * 16) * BK + a_hi));
#pragma unroll
    for (int p = 0; p < 4; p++)
        b_sw[p] = (uint32_t)A_STAGE + SWZ((uint32_t)((b_row + p * 16) * BK + b_hi));

    for (int kt = 0; kt < K_TILES; kt++) {
        CP_WAIT(0);
        __syncthreads();

        if (kt + 1 < K_TILES) {
            load_stage((kt + 1) & 1, kt + 1);
            CP_COMMIT();
        }

        const uint32_t abase = sbase + (kt & 1) * STAGE_BYTES;

#pragma unroll
        for (int s = 0; s < BK / 32; s++) {       // 4 k-steps of 32 fp8
            const uint32_t sx32 = (uint32_t)(s << 5);
            uint32_t af[2][4];
#pragma unroll
            for (int mt = 0; mt < 2; mt++)
                ldmatrix_x4(af[mt], abase + (a_sw[mt] ^ sx32));
            uint32_t bf[4][4];
#pragma unroll
            for (int p = 0; p < 4; p++)
                ldmatrix_x4(bf[p], abase + (b_sw[p] ^ sx32));
#pragma unroll
            for (int mt = 0; mt < 2; mt++)
#pragma unroll
                for (int p = 0; p < 4; p++) {
                    mma_e4m3(acc[mt][2 * p + 0], af[mt], &bf[p][0]);
                    mma_e4m3(acc[mt][2 * p + 1], af[mt], &bf[p][2]);
                }
        }
    }

    // Epilogue
    const float inv = 1.0f / (__ldg(sx) * __ldg(sw));
    const int r0 = m0 + warp_m * 32 + (lane >> 2);
    const int c0 = n0 + warp_n * 64 + (lane & 3) * 2;
#pragma unroll
    for (int mt = 0; mt < 2; mt++) {
#pragma unroll
        for (int nt = 0; nt < 8; nt++) {
            int row = r0 + mt * 16;
            int col = c0 + nt * 8;
            float2 v0 = { acc[mt][nt][0] * inv, acc[mt][nt][1] * inv };
            float2 v1 = { acc[mt][nt][2] * inv, acc[mt][nt][3] * inv };
            *reinterpret_cast<float2*>(out + (size_t)row * N_TOTAL + col) = v0;
            *reinterpret_cast<float2*>(out + (size_t)(row + 8) * N_TOTAL + col) = v1;
        }
    }
}

// ============================================================================
// kernel_launch
// ============================================================================
extern "C" void kernel_launch(void* const* d_in, const int* in_sizes, int n_in,
                              void* d_out, int out_size)
{
    const float* input  = (const float*)d_in[0];
    const float* weight = (const float*)d_in[1];
    const float* sx     = (const float*)d_in[2];  // input_scale_e4m3
    const float* sw     = (const float*)d_in[3];  // weight_scale_e4m3
    float* out = (float*)d_out;

    void* aq = nullptr;
    void* wq = nullptr;
    cudaGetSymbolAddress(&aq, g_Aq);
    cudaGetSymbolAddress(&wq, g_Wq);

    {
        int nthreads = A_T4 + W_T4;   // 2,097,152
        quant_both_kernel<<<nthreads / 256, 256>>>(input, weight, sx, sw,
                                                   (uint8_t*)aq, (uint8_t*)wq);
    }

    cudaFuncSetAttribute(fp8_gemm_kernel,
                         cudaFuncAttributeMaxDynamicSharedMemorySize, SMEM_TOTAL);
    dim3 grid(N_TOTAL / BN, M_TOTAL / BM);
    fp8_gemm_kernel<<<grid, 256, SMEM_TOTAL>>>(
        (const uint8_t*)aq, (const uint8_t*)wq, out, sx, sw);
}